// round 5
// baseline (speedup 1.0000x reference)
#include <cuda_runtime.h>
#include <math.h>

#define NFFT   4096
#define NHALF  2048
#define NSPEC  2049
#define CCH    512
#define NPIX   784
#define NB     8
#define SLOTS  36
#define DOUT   8705
#define NTHR   512

#define NTW    1024     // quarter-wave twiddle table; tw[k+1024] = -i*tw[k]
#define APAD   4224     // 4096 + 4096/32 padding
#define CPAD   2112     // 2048 + 64
#define SWI(i) ((i) + ((i) >> 5))

__device__ float2 g_acc2[NB][NSPEC];
__device__ float2 g_acc3[NB][NSPEC];
__device__ float  g_first[NB][CCH];

__device__ __forceinline__ float2 cmul(float2 a, float2 b) {
    return make_float2(a.x * b.x - a.y * b.y, a.x * b.y + a.y * b.x);
}

// twiddle fetch for index k in [0,2048): quarter-wave fixup
__device__ __forceinline__ float2 twget(const float2* __restrict__ T, int k) {
    float2 t = T[k & (NTW - 1)];
    if (k & NTW) t = make_float2(t.y, -t.x);   // multiply by -i
    return t;
}

// ---------------- Stockham radix-8 stage (swizzled smem) ----------------
template<bool INV>
__device__ __forceinline__ void stage8(const float2* __restrict__ src,
                                       float2* __restrict__ dst,
                                       const float2* __restrict__ tw,
                                       int sh, int ls, int eighth,
                                       int tid, int nt)
{
    const float CC = 0.70710678118654752f;
    for (int t = tid; t < eighth; t += nt) {
        int p = t >> ls;
        int q = t & ((1 << ls) - 1);
        float2 x0 = src[SWI(t)];
        float2 x1 = src[SWI(t + eighth)];
        float2 x2 = src[SWI(t + 2 * eighth)];
        float2 x3 = src[SWI(t + 3 * eighth)];
        float2 x4 = src[SWI(t + 4 * eighth)];
        float2 x5 = src[SWI(t + 5 * eighth)];
        float2 x6 = src[SWI(t + 6 * eighth)];
        float2 x7 = src[SWI(t + 7 * eighth)];

        float2 u0 = {x0.x + x4.x, x0.y + x4.y};
        float2 u1 = {x0.x - x4.x, x0.y - x4.y};
        float2 u2 = {x2.x + x6.x, x2.y + x6.y};
        float2 u3 = {x2.x - x6.x, x2.y - x6.y};
        float2 e0 = {u0.x + u2.x, u0.y + u2.y};
        float2 e2 = {u0.x - u2.x, u0.y - u2.y};
        float2 j3 = {-u3.y, u3.x};
        float2 e1, e3;
        if (!INV) { e1 = {u1.x - j3.x, u1.y - j3.y}; e3 = {u1.x + j3.x, u1.y + j3.y}; }
        else      { e1 = {u1.x + j3.x, u1.y + j3.y}; e3 = {u1.x - j3.x, u1.y - j3.y}; }

        float2 v0 = {x1.x + x5.x, x1.y + x5.y};
        float2 v1 = {x1.x - x5.x, x1.y - x5.y};
        float2 v2 = {x3.x + x7.x, x3.y + x7.y};
        float2 v3 = {x3.x - x7.x, x3.y - x7.y};
        float2 o0 = {v0.x + v2.x, v0.y + v2.y};
        float2 o2 = {v0.x - v2.x, v0.y - v2.y};
        float2 k3 = {-v3.y, v3.x};
        float2 o1, o3;
        if (!INV) { o1 = {v1.x - k3.x, v1.y - k3.y}; o3 = {v1.x + k3.x, v1.y + k3.y}; }
        else      { o1 = {v1.x + k3.x, v1.y + k3.y}; o3 = {v1.x - k3.x, v1.y - k3.y}; }

        float2 t1, t2, t3;
        if (!INV) {
            t1 = { CC * (o1.x + o1.y),  CC * (o1.y - o1.x) };
            t2 = { o2.y, -o2.x };
            t3 = { CC * (o3.y - o3.x), -CC * (o3.x + o3.y) };
        } else {
            t1 = { CC * (o1.x - o1.y),  CC * (o1.y + o1.x) };
            t2 = { -o2.y, o2.x };
            t3 = { -CC * (o3.x + o3.y), CC * (o3.x - o3.y) };
        }
        float2 y0 = {e0.x + o0.x, e0.y + o0.y};
        float2 y4 = {e0.x - o0.x, e0.y - o0.y};
        float2 y1 = {e1.x + t1.x, e1.y + t1.y};
        float2 y5 = {e1.x - t1.x, e1.y - t1.y};
        float2 y2 = {e2.x + t2.x, e2.y + t2.y};
        float2 y6 = {e2.x - t2.x, e2.y - t2.y};
        float2 y3 = {e3.x + t3.x, e3.y + t3.y};
        float2 y7 = {e3.x - t3.x, e3.y - t3.y};

        float2 w1 = tw[p << sh];                 // idx <= 511
        float2 w2 = tw[(2 * p) << sh];           // idx <= 1022
        float2 w4 = twget(tw, (4 * p) << sh);    // idx <= 2044, may need fixup
        if (INV) { w1.y = -w1.y; w2.y = -w2.y; w4.y = -w4.y; }
        float2 w3 = cmul(w1, w2);
        float2 w5 = cmul(w1, w4);
        float2 w6 = cmul(w2, w4);
        float2 w7 = cmul(w3, w4);
        y1 = cmul(y1, w1); y2 = cmul(y2, w2); y3 = cmul(y3, w3);
        y4 = cmul(y4, w4); y5 = cmul(y5, w5); y6 = cmul(y6, w6); y7 = cmul(y7, w7);

        int s = 1 << ls;
        int o = q + (p << (ls + 3));
        dst[SWI(o)]         = y0;
        dst[SWI(o + s)]     = y1;
        dst[SWI(o + 2*s)]   = y2;
        dst[SWI(o + 3*s)]   = y3;
        dst[SWI(o + 4*s)]   = y4;
        dst[SWI(o + 5*s)]   = y5;
        dst[SWI(o + 6*s)]   = y6;
        dst[SWI(o + 7*s)]   = y7;
    }
}

// ---------------- radix-4 tail stage (all twiddle indices are 0 here) --------
template<bool INV>
__device__ __forceinline__ void stage4(const float2* __restrict__ src,
                                       float2* __restrict__ dst,
                                       const float2* __restrict__ tw,
                                       int sh, int ls, int quarter,
                                       int tid, int nt)
{
    for (int t = tid; t < quarter; t += nt) {
        int p = t >> ls;
        int q = t & ((1 << ls) - 1);
        float2 a = src[SWI(t)];
        float2 b = src[SWI(t + quarter)];
        float2 c = src[SWI(t + 2 * quarter)];
        float2 d = src[SWI(t + 3 * quarter)];
        float2 apc  = {a.x + c.x, a.y + c.y};
        float2 amc  = {a.x - c.x, a.y - c.y};
        float2 bpd  = {b.x + d.x, b.y + d.y};
        float2 jbmd = {-(b.y - d.y), b.x - d.x};
        float2 y0 = {apc.x + bpd.x, apc.y + bpd.y};
        float2 y2 = {apc.x - bpd.x, apc.y - bpd.y};
        float2 y1, y3;
        if (!INV) { y1 = {amc.x - jbmd.x, amc.y - jbmd.y}; y3 = {amc.x + jbmd.x, amc.y + jbmd.y}; }
        else      { y1 = {amc.x + jbmd.x, amc.y + jbmd.y}; y3 = {amc.x - jbmd.x, amc.y - jbmd.y}; }
        int ti = p << sh;
        float2 w1 = twget(tw, ti);
        float2 w2 = twget(tw, 2 * ti);
        float2 w3 = cmul(w1, w2);
        if (INV) { w1.y = -w1.y; w2.y = -w2.y; w3.y = -w3.y; }
        y1 = cmul(y1, w1);
        y2 = cmul(y2, w2);
        y3 = cmul(y3, w3);
        int s = 1 << ls;
        int o = q + (p << (ls + 2));
        dst[SWI(o)]       = y0;
        dst[SWI(o + s)]   = y1;
        dst[SWI(o + 2*s)] = y2;
        dst[SWI(o + 3*s)] = y3;
    }
}

// 4096-pt FFT, 4 radix-8 stages, in-place over A (B scratch). (finalize path)
template<bool INV>
__device__ void fft4096_r8(float2* A, float2* B, const float2* tw, int tid, int nt)
{
    stage8<INV>(A, B, tw, 0, 0, 512, tid, nt); __syncthreads();
    stage8<INV>(B, A, tw, 3, 3, 512, tid, nt); __syncthreads();
    stage8<INV>(A, B, tw, 6, 6, 512, tid, nt); __syncthreads();
    stage8<INV>(B, A, tw, 9, 9, 512, tid, nt); __syncthreads();
}

__device__ __forceinline__ void binprod(float2 Zk, float2 Zm, float2 Gk, float2 Gm,
                                        float2 w, float2& P2, float2& P3)
{
    float2 F0 = { 0.5f * (Zk.x + Zm.x),  0.5f * (Zk.y - Zm.y) };
    float2 F1 = { 0.5f * (Zk.y + Zm.y), -0.5f * (Zk.x - Zm.x) };
    float2 E  = { 0.5f * (Gk.x + Gm.x),  0.5f * (Gk.y - Gm.y) };
    float2 O  = { 0.5f * (Gk.y + Gm.y), -0.5f * (Gk.x - Gm.x) };
    float2 F2 = { E.x + w.x * O.x - w.y * O.y, E.y + w.x * O.y + w.y * O.x };
    P2 = cmul(F0, F1);
    P3 = cmul(P2, F2);
}

__global__ void zero_kernel()
{
    int i = blockIdx.x * blockDim.x + threadIdx.x;
    int n = NB * NSPEC * 2;
    if (i < n) {
        ((float*)g_acc2)[i] = 0.f;
        ((float*)g_acc3)[i] = 0.f;
    }
}

__global__ void first_kernel(const float* __restrict__ x)
{
    int b = blockIdx.x;
    int c = threadIdx.x;
    const float* p = x + (size_t)b * NPIX * CCH + c;
    float s = 0.f;
    #pragma unroll 8
    for (int i = 0; i < NPIX; i++) s += p[(size_t)i * CCH];
    g_first[b][c] = s;
}

__global__ void __launch_bounds__(NTHR, 2)
poly_sketch_kernel(const float* __restrict__ x,
                   const int* __restrict__ h_idx,
                   const int* __restrict__ s_bits)
{
    extern __shared__ float2 smem[];
    float2* tw = smem;                  // NTW
    float2* A  = smem + NTW;            // APAD
    float2* B  = A + APAD;              // APAD
    float2* Cc = B + APAD;              // CPAD
    float2* D  = Cc + CPAD;             // CPAD

    int tid  = threadIdx.x;
    int b    = blockIdx.x / SLOTS;
    int slot = blockIdx.x % SLOTS;

    for (int j = tid; j < NTW; j += NTHR) {
        float sn, cs;
        sincospif(-(float)j * (1.0f / 2048.0f), &sn, &cs);
        tw[j] = make_float2(cs, sn);
    }
    for (int j = tid; j < APAD; j += NTHR) A[j] = make_float2(0.f, 0.f);
    for (int j = tid; j < CPAD; j += NTHR) Cc[j] = make_float2(0.f, 0.f);

    int   h0 = h_idx[tid],          h1 = h_idx[CCH + tid],        h2 = h_idx[2 * CCH + tid];
    float s0 = (float)(2 * s_bits[tid] - 1);
    float s1 = (float)(2 * s_bits[CCH + tid] - 1);
    float s2 = (float)(2 * s_bits[2 * CCH + tid] - 1);
    int cfa = 2 * SWI(h2 >> 1) + (h2 & 1);
    __syncthreads();

    float2 a2[4], a3[4];
    #pragma unroll
    for (int i = 0; i < 4; i++) { a2[i] = make_float2(0.f, 0.f); a3[i] = make_float2(0.f, 0.f); }

    for (int pix = slot; pix < NPIX; pix += SLOTS) {
        float xv = x[((size_t)(b * NPIX + pix)) * CCH + tid];

        atomicAdd(&A[SWI(h0)].x, xv * s0);
        atomicAdd(&A[SWI(h1)].y, xv * s1);
        atomicAdd(&((float*)Cc)[cfa], xv * s2);
        __syncthreads();

        // interleaved FFT phases: 4096-pt (A<->B) + 2048-pt (Cc<->D) per barrier
        stage8<false>(A, B, tw, 0, 0, 512, tid, NTHR);
        stage8<false>(Cc, D, tw, 1, 0, 256, tid, NTHR);
        __syncthreads();
        stage8<false>(B, A, tw, 3, 3, 512, tid, NTHR);
        stage8<false>(D, Cc, tw, 4, 3, 256, tid, NTHR);
        __syncthreads();
        stage8<false>(A, B, tw, 6, 6, 512, tid, NTHR);
        stage8<false>(Cc, D, tw, 7, 6, 256, tid, NTHR);
        __syncthreads();
        stage8<false>(B, A, tw, 9, 9, 512, tid, NTHR);
        stage4<false>(D, Cc, tw, 10, 9, 512, tid, NTHR);
        __syncthreads();
        // Z (s0+i*s1 spectrum) in A; G (s2 even/odd-packed spectrum) in Cc

        #pragma unroll
        for (int jj = 0; jj < 2; jj++) {
            int k  = tid + jj * 512;
            int km = (NFFT - k) & (NFFT - 1);
            int kb = 2048 - k;
            int jm = (NHALF - k) & (NHALF - 1);
            float2 Zk  = A[SWI(k)];
            float2 Zm  = A[SWI(km)];
            float2 Zk2 = A[SWI(kb)];
            float2 Zm2 = A[SWI(2048 + k)];
            float2 Gk  = Cc[SWI(k)];
            float2 Gm  = Cc[SWI(jm)];
            float2 w   = tw[k & (NTW - 1)];
            if (k & NTW) w = make_float2(w.y, -w.x);    // k in [1024,2048)
            float2 P2a, P3a, P2b, P3b;
            binprod(Zk,  Zm,  Gk, Gm, w, P2a, P3a);
            binprod(Zk2, Zm2, Gm, Gk, make_float2(-w.x, w.y), P2b, P3b);
            a2[2*jj].x   += P2a.x; a2[2*jj].y   += P2a.y;
            a3[2*jj].x   += P3a.x; a3[2*jj].y   += P3a.y;
            a2[2*jj+1].x += P2b.x; a2[2*jj+1].y += P2b.y;
            a3[2*jj+1].x += P3b.x; a3[2*jj+1].y += P3b.y;
            float2 z = make_float2(0.f, 0.f);
            A[SWI(k)] = z; A[SWI(km)] = z; A[SWI(kb)] = z; A[SWI(2048 + k)] = z;
            Cc[SWI(k)] = z; Cc[SWI(jm)] = z;
        }
        if (tid == 0) {                   // self-paired bin 1024: straight to global
            float2 Zk = A[SWI(1024)], Zm = A[SWI(3072)];
            float2 Gk = Cc[SWI(1024)];
            float2 P2e, P3e;
            binprod(Zk, Zm, Gk, Gk, make_float2(0.f, -1.f), P2e, P3e);
            atomicAdd(&g_acc2[b][1024].x, P2e.x);
            atomicAdd(&g_acc2[b][1024].y, P2e.y);
            atomicAdd(&g_acc3[b][1024].x, P3e.x);
            atomicAdd(&g_acc3[b][1024].y, P3e.y);
            float2 z = make_float2(0.f, 0.f);
            A[SWI(1024)] = z; A[SWI(3072)] = z; Cc[SWI(1024)] = z;
        }
        __syncthreads();
    }

    int bins[4] = { tid, 2048 - tid, tid + 512, 1536 - tid };
    #pragma unroll
    for (int i = 0; i < 4; i++) {
        atomicAdd(&g_acc2[b][bins[i]].x, a2[i].x);
        atomicAdd(&g_acc2[b][bins[i]].y, a2[i].y);
        atomicAdd(&g_acc3[b][bins[i]].x, a3[i].x);
        atomicAdd(&g_acc3[b][bins[i]].y, a3[i].y);
    }
}

__global__ void __launch_bounds__(NTHR, 1)
finalize_kernel(const float* __restrict__ alpha, float* __restrict__ out)
{
    extern __shared__ float2 smem[];
    float2* tw  = smem;                 // NTW
    float2* A   = smem + NTW;
    float2* B   = A + APAD;
    float*  phi = (float*)(B + APAD);   // 8712 floats
    __shared__ float red[17];

    int tid = threadIdx.x;
    int b   = blockIdx.x;

    for (int j = tid; j < NTW; j += NTHR) {
        float sn, cs;
        sincospif(-(float)j * (1.0f / 2048.0f), &sn, &cs);
        tw[j] = make_float2(cs, sn);
    }
    __syncthreads();

    const float inv_n = 1.0f / ((float)NPIX * (float)NFFT);

    for (int i = tid; i < NFFT; i += NTHR) {
        if (i <= NHALF) A[SWI(i)] = g_acc2[b][i];
        else { float2 v = g_acc2[b][NFFT - i]; A[SWI(i)] = make_float2(v.x, -v.y); }
    }
    __syncthreads();
    fft4096_r8<true>(A, B, tw, tid, NTHR);
    {
        float a2c = alpha[2] * inv_n;
        for (int i = tid; i < NFFT; i += NTHR) phi[513 + i] = A[SWI(i)].x * a2c;
    }
    __syncthreads();

    for (int i = tid; i < NFFT; i += NTHR) {
        if (i <= NHALF) A[SWI(i)] = g_acc3[b][i];
        else { float2 v = g_acc3[b][NFFT - i]; A[SWI(i)] = make_float2(v.x, -v.y); }
    }
    __syncthreads();
    fft4096_r8<true>(A, B, tw, tid, NTHR);
    {
        float a3c = alpha[3] * inv_n;
        for (int i = tid; i < NFFT; i += NTHR) phi[513 + NFFT + i] = A[SWI(i)].x * a3c;
    }

    if (tid == 0) phi[0] = alpha[0];
    phi[1 + tid] = alpha[1] * g_first[b][tid] * (1.0f / (float)NPIX);
    __syncthreads();

    float lsum = 0.f;
    for (int i = tid; i < DOUT; i += NTHR) {
        float v = phi[i];
        float r;
        if (v > 0.f)      r =  sqrtf(v + 1e-12f);
        else if (v < 0.f) r = -sqrtf(-v + 1e-12f);
        else              r = 0.f;
        phi[i] = r;
        lsum += r * r;
    }
    #pragma unroll
    for (int off = 16; off > 0; off >>= 1)
        lsum += __shfl_down_sync(0xffffffffu, lsum, off);
    if ((tid & 31) == 0) red[tid >> 5] = lsum;
    __syncthreads();
    if (tid == 0) {
        float s = 0.f;
        #pragma unroll
        for (int k = 0; k < 16; k++) s += red[k];
        red[16] = 1.0f / sqrtf(s);
    }
    __syncthreads();
    float rn = red[16];
    for (int i = tid; i < DOUT; i += NTHR)
        out[(size_t)b * DOUT + i] = phi[i] * rn;
}

extern "C" void kernel_launch(void* const* d_in, const int* in_sizes, int n_in,
                              void* d_out, int out_size)
{
    const float* x     = (const float*)d_in[0];
    const float* alpha = (const float*)d_in[1];
    const int*   h     = (const int*)d_in[2];
    const int*   sb    = (const int*)d_in[3];
    float*       out   = (float*)d_out;

    const int MAIN_SMEM = (NTW + 2 * APAD + 2 * CPAD) * (int)sizeof(float2); // 109568
    const int FIN_SMEM  = (NTW + 2 * APAD) * (int)sizeof(float2) + 8712 * 4; // 110624

    cudaFuncSetAttribute(poly_sketch_kernel,
                         cudaFuncAttributeMaxDynamicSharedMemorySize, MAIN_SMEM);
    cudaFuncSetAttribute(finalize_kernel,
                         cudaFuncAttributeMaxDynamicSharedMemorySize, FIN_SMEM);

    zero_kernel<<<(NB * NSPEC * 2 + 255) / 256, 256>>>();
    first_kernel<<<NB, CCH>>>(x);
    poly_sketch_kernel<<<NB * SLOTS, NTHR, MAIN_SMEM>>>(x, h, sb);
    finalize_kernel<<<NB, NTHR, FIN_SMEM>>>(alpha, out);
}